// round 9
// baseline (speedup 1.0000x reference)
#include <cuda_runtime.h>
#include <cuda_bf16.h>
#include <math.h>
#include <cstdint>

// Problem constants (fixed by reference setup_inputs)
#define BSZ   4096
#define D0    2048
#define D1    128
#define NTOT  8192
#define TM    128
#define NT    (NTOT / TM)            // 64
#define NTILES_TRI (NT * (NT + 1) / 2)  // 2080
#define PERSIST_GRID 296             // 2 CTAs/SM x 148 SMs
// bf16 screen threshold vs exact threshold (margin covers bf16 dot error ~ +-6).
#define SCREEN_T 145.0f
#define EXACT_T  130.0f

#define SPAD1 136                     // smem row stride (bf16 elems): 272B, 16B-aligned
#define QCAP  1024

// dynamic smem layout (bytes)
#define SM_A     0
#define SM_B     (128 * SPAD1 * 2)                  // 34816
#define SM_SQB   (SM_B + 128 * SPAD1 * 2)           // 69632  (2 buffers x 512B)
#define SM_WRED  (SM_SQB + 1024)                    // 70656  (16 floats)
#define SM_QUEUE (SM_WRED + 16 * 4)                 // 70720
#define SM_QCNT  (SM_QUEUE + QCAP * 4)              // 74816
#define SM_TOTAL (SM_QCNT + 32)                     // 74848

// ---- scratch (allocation-free rule: __device__ globals) ----
__device__ float  g_sq0[NTOT];
__device__ float  g_sq1[NTOT];
__device__ float  g_colsum[D0];
__device__ double g_sum_sq0;
__device__ double g_acc;
__device__ float  g_inv_bw[5];
__device__ __nv_bfloat16 g_x1[(size_t)NTOT * D1];   // bf16 copy of feature1 (2 MB)

__device__ __forceinline__ uint32_t smem_u32(const void* p) {
    uint32_t a;
    asm("{ .reg .u64 t; cvta.to.shared.u64 t, %1; cvt.u32.u64 %0, t; }"
        : "=r"(a) : "l"(p));
    return a;
}

// Cold path: exact scalar recompute (queue overflow only; keeps hot regs lean)
__device__ __noinline__ float pair_exact_scalar(
    int aa, int bb,
    const float* __restrict__ src0, const float* __restrict__ tar0,
    const float* __restrict__ src1, const float* __restrict__ tar1)
{
    const float* ra1 = (aa < BSZ) ? (src1 + (size_t)aa * D1)
                                  : (tar1 + (size_t)(aa - BSZ) * D1);
    const float* rb1 = (bb < BSZ) ? (src1 + (size_t)bb * D1)
                                  : (tar1 + (size_t)(bb - BSZ) * D1);
    float dp1 = 0.0f;
    for (int dd = 0; dd < D1; dd += 4) {
        float4 x = *(const float4*)(ra1 + dd);
        float4 y = *(const float4*)(rb1 + dd);
        dp1 += x.x * y.x + x.y * y.y + x.z * y.z + x.w * y.w;
    }
    float l21 = g_sq1[aa] + g_sq1[bb] - 2.0f * dp1;
    if (l21 >= EXACT_T) return 0.0f;
    const float* ra0 = (aa < BSZ) ? (src0 + (size_t)aa * D0)
                                  : (tar0 + (size_t)(aa - BSZ) * D0);
    const float* rb0 = (bb < BSZ) ? (src0 + (size_t)bb * D0)
                                  : (tar0 + (size_t)(bb - BSZ) * D0);
    float dp0 = 0.0f;
    for (int dd = 0; dd < D0; dd += 4) {
        float4 x = *(const float4*)(ra0 + dd);
        float4 y = *(const float4*)(rb0 + dd);
        dp0 += x.x * y.x + x.y * y.y + x.z * y.z + x.w * y.w;
    }
    float l20 = g_sq0[aa] + g_sq0[bb] - 2.0f * dp0;
    float k0v = 0.0f;
#pragma unroll
    for (int q = 0; q < 5; q++) k0v += expf(-l20 * g_inv_bw[q]);
    return k0v * expf(-l21 * (1.0f / 1.68f));
}

// ---------------------------------------------------------------------------
// K1: zero accumulators + convert feature1 to bf16 + per-row sq1
// 256 CTAs x 256 threads; each warp handles 4 rows (lane = float4 of the row)
// ---------------------------------------------------------------------------
__global__ __launch_bounds__(256) void k_pre(
    const float* __restrict__ src1, const float* __restrict__ tar1)
{
    int bid = blockIdx.x;
    int t = threadIdx.x;
    int w = t >> 5, l = t & 31;

    // distributed zeroing
    if (bid < 8)  g_colsum[bid * 256 + t] = 0.0f;
    else if (bid < 40) g_sq0[(bid - 8) * 256 + t] = 0.0f;
    if (bid == 0 && t == 0) { g_sum_sq0 = 0.0; g_acc = 0.0; }

    int base = bid * 32 + w * 4;
#pragma unroll
    for (int rr = 0; rr < 4; rr++) {
        int n = base + rr;
        const float* r1 = (n < BSZ) ? (src1 + (size_t)n * D1)
                                    : (tar1 + (size_t)(n - BSZ) * D1);
        float4 v = ((const float4*)r1)[l];
        __nv_bfloat162 lo = __floats2bfloat162_rn(v.x, v.y);
        __nv_bfloat162 hi = __floats2bfloat162_rn(v.z, v.w);
        uint2 pk;
        pk.x = *(uint32_t*)&lo;
        pk.y = *(uint32_t*)&hi;
        *(uint2*)(g_x1 + (size_t)n * D1 + l * 4) = pk;
        float s = v.x * v.x + v.y * v.y + v.z * v.z + v.w * v.w;
#pragma unroll
        for (int off = 16; off; off >>= 1)
            s += __shfl_xor_sync(0xffffffffu, s, off);
        if (l == 0) g_sq1[n] = s;
    }
}

// ---------------------------------------------------------------------------
// K2: fused single pass over feature0 (64 MB): row sq0 + col sums + total sq
// grid (8, 64): x = 256-col block, y = 128-row chunk; warp w owns 16 rows.
// ---------------------------------------------------------------------------
__global__ __launch_bounds__(256) void k_f0(
    const float* __restrict__ src0, const float* __restrict__ tar0)
{
    int w = threadIdx.x >> 5, l = threadIdx.x & 31;
    int d0 = blockIdx.x * 256;
    int nbase = blockIdx.y * 128 + w * 16;
    float colacc[8] = {};
    double wsum = 0.0;
#pragma unroll 2
    for (int rr = 0; rr < 16; rr++) {
        int n = nbase + rr;
        const float* p = (n < BSZ) ? (src0 + (size_t)n * D0)
                                   : (tar0 + (size_t)(n - BSZ) * D0);
        float sq = 0.0f;
#pragma unroll
        for (int j = 0; j < 8; j++) {
            float v = p[d0 + l + j * 32];
            sq += v * v;
            colacc[j] += v;
        }
#pragma unroll
        for (int off = 16; off; off >>= 1)
            sq += __shfl_xor_sync(0xffffffffu, sq, off);
        if (l == 0) { atomicAdd(&g_sq0[n], sq); wsum += (double)sq; }
    }
    if (l == 0) atomicAdd(&g_sum_sq0, wsum);
#pragma unroll
    for (int j = 0; j < 8; j++)
        atomicAdd(&g_colsum[d0 + l + j * 32], colacc[j]);
}

// ---------------------------------------------------------------------------
// K3: finalize bandwidth: sum_l2 = 2N*sum_sq0 - 2*||colsum||^2
// ---------------------------------------------------------------------------
__global__ __launch_bounds__(1024) void k_bw() {
    int t = threadIdx.x;
    double s = 0.0;
#pragma unroll
    for (int j = 0; j < 2; j++) {
        double c = (double)g_colsum[t + j * 1024];
        s += c * c;
    }
#pragma unroll
    for (int off = 16; off; off >>= 1)
        s += __shfl_xor_sync(0xffffffffu, s, off);
    __shared__ double red[32];
    if ((t & 31) == 0) red[t >> 5] = s;
    __syncthreads();
    if (t == 0) {
        double tot = 0.0;
#pragma unroll
        for (int i = 0; i < 32; i++) tot += red[i];
        double sum_l2 = 2.0 * (double)NTOT * g_sum_sq0 - 2.0 * tot;
        double bw = sum_l2 / ((double)NTOT * (double)NTOT - (double)NTOT) / 4.0;
#pragma unroll
        for (int i = 0; i < 5; i++)
            g_inv_bw[i] = (float)(1.0 / (bw * (double)(1 << i)));
    }
}

__device__ __forceinline__ void unrank_tri(int idx, int& by, int& bx) {
    int r = (int)((2.0 * NT + 1.0
                   - sqrt((2.0 * NT + 1.0) * (2.0 * NT + 1.0) - 8.0 * idx)) * 0.5);
    if (r < 0) r = 0;
    while (r * NT - r * (r - 1) / 2 > idx) r--;
    while ((r + 1) * NT - (r + 1) * r / 2 <= idx) r++;
    by = r;
    bx = r + (idx - (r * NT - r * (r - 1) / 2));
}

// ---------------------------------------------------------------------------
// K4: persistent bf16 HMMA screening GEMM with cross-tile cp.async prefetch.
// 296 CTAs x 512 threads (16 warps, 4x4 warp grid, warp tile 32x32), 2 CTAs/SM
// -> 32 warps/SM. Single-buffered A/B (prefetch overlaps epilogue),
// double-buffered sqb. Queue-based warp-cooperative exact epilogue.
// ---------------------------------------------------------------------------
__global__ __launch_bounds__(512, 2) void k_tile(
    const float* __restrict__ src0, const float* __restrict__ tar0,
    const float* __restrict__ src1, const float* __restrict__ tar1)
{
    extern __shared__ char dsm[];
    float*    sqbuf  = (float*)(dsm + SM_SQB);      // [2][128]
    float*    wred   = (float*)(dsm + SM_WRED);
    uint32_t* queue  = (uint32_t*)(dsm + SM_QUEUE);
    uint32_t* qcount = (uint32_t*)(dsm + SM_QCNT);

    int tid = threadIdx.x;
    int wid = tid >> 5, lane = tid & 31;
    int wy = wid >> 2, wx = wid & 3;    // 4x4 warp grid, warp tile 32x32

    uint32_t sAb = smem_u32(dsm + SM_A);
    uint32_t sBb = smem_u32(dsm + SM_B);
    uint32_t sSq = smem_u32(sqbuf);

    uint32_t aRow = (uint32_t)(wy * 32 + (lane & 15));
    uint32_t aKof = (uint32_t)((lane >> 4) * 8);
    uint32_t bRowBase = (uint32_t)(wx * 32 + ((lane >> 3) & 1) * 8 + (lane & 7));
    uint32_t bKof = (uint32_t)((lane >> 4) * 8);

    if (tid == 0) *qcount = 0;

    int idx = blockIdx.x;
    int by, bx;
    unrank_tri(idx, by, bx);

    // initial fill (sq buffer 0)
    {
        int arow0 = by * TM, brow0 = bx * TM;
        for (int c = tid; c < 2048; c += 512) {
            int row = c >> 4, cc = c & 15;
            uint32_t da = sAb + (uint32_t)(row * SPAD1 + cc * 8) * 2;
            uint32_t db = sBb + (uint32_t)(row * SPAD1 + cc * 8) * 2;
            const void* ga = g_x1 + (size_t)(arow0 + row) * D1 + cc * 8;
            const void* gb = g_x1 + (size_t)(brow0 + row) * D1 + cc * 8;
            asm volatile("cp.async.cg.shared.global [%0], [%1], 16;" :: "r"(da), "l"(ga));
            asm volatile("cp.async.cg.shared.global [%0], [%1], 16;" :: "r"(db), "l"(gb));
        }
        if (tid < 32) {
            uint32_t ds = sSq + (uint32_t)tid * 16;
            const void* gs = g_sq1 + brow0 + tid * 4;
            asm volatile("cp.async.ca.shared.global [%0], [%1], 16;" :: "r"(ds), "l"(gs));
        }
        asm volatile("cp.async.commit_group;" ::: "memory");
    }

    int iter = 0;
    for (; idx < NTILES_TRI; idx += PERSIST_GRID, iter++) {
        int buf = iter & 1;
        int arow0 = by * TM, brow0 = bx * TM;
        float* sqb = sqbuf + buf * 128;

        asm volatile("cp.async.wait_group 0;" ::: "memory");
        __syncthreads();

        // --- MMA mainloop: 8 K16 steps, warp tile 32x32 ---
        float acc[2][4][4];
#pragma unroll
        for (int mt = 0; mt < 2; mt++)
#pragma unroll
            for (int nt = 0; nt < 4; nt++)
#pragma unroll
                for (int v = 0; v < 4; v++) acc[mt][nt][v] = 0.0f;

#pragma unroll
        for (int ks = 0; ks < 8; ks++) {
            uint32_t a[2][4];
#pragma unroll
            for (int mt = 0; mt < 2; mt++) {
                uint32_t addr = sAb + ((aRow + mt * 16) * SPAD1 + ks * 16 + aKof) * 2;
                asm volatile(
                    "ldmatrix.sync.aligned.m8n8.x4.shared.b16 {%0,%1,%2,%3}, [%4];"
                    : "=r"(a[mt][0]), "=r"(a[mt][1]), "=r"(a[mt][2]), "=r"(a[mt][3])
                    : "r"(addr));
            }
            uint32_t b[2][4];
#pragma unroll
            for (int np = 0; np < 2; np++) {
                uint32_t addr = sBb + ((bRowBase + np * 16) * SPAD1 + ks * 16 + bKof) * 2;
                asm volatile(
                    "ldmatrix.sync.aligned.m8n8.x4.shared.b16 {%0,%1,%2,%3}, [%4];"
                    : "=r"(b[np][0]), "=r"(b[np][1]), "=r"(b[np][2]), "=r"(b[np][3])
                    : "r"(addr));
            }
#pragma unroll
            for (int mt = 0; mt < 2; mt++)
#pragma unroll
                for (int nt = 0; nt < 4; nt++) {
                    uint32_t b0 = b[nt >> 1][(nt & 1)];
                    uint32_t b1 = b[nt >> 1][(nt & 1) + 2];
                    float* c = acc[mt][nt];
                    asm volatile(
                        "mma.sync.aligned.m16n8k16.row.col.f32.bf16.bf16.f32 "
                        "{%0,%1,%2,%3}, {%4,%5,%6,%7}, {%8,%9}, {%0,%1,%2,%3};"
                        : "+f"(c[0]), "+f"(c[1]), "+f"(c[2]), "+f"(c[3])
                        : "r"(a[mt][0]), "r"(a[mt][1]), "r"(a[mt][2]), "r"(a[mt][3]),
                          "r"(b0), "r"(b1));
                }
        }
        __syncthreads();   // all warps done reading A/B -> safe to overwrite

        // --- prefetch next tile (overlaps epilogue) ---
        int nby = 0, nbx = 0;
        {
            int nidx = idx + PERSIST_GRID;
            if (nidx < NTILES_TRI) {
                unrank_tri(nidx, nby, nbx);
                int na = nby * TM, nb = nbx * TM;
                for (int c = tid; c < 2048; c += 512) {
                    int row = c >> 4, cc = c & 15;
                    uint32_t da = sAb + (uint32_t)(row * SPAD1 + cc * 8) * 2;
                    uint32_t db = sBb + (uint32_t)(row * SPAD1 + cc * 8) * 2;
                    const void* ga = g_x1 + (size_t)(na + row) * D1 + cc * 8;
                    const void* gb = g_x1 + (size_t)(nb + row) * D1 + cc * 8;
                    asm volatile("cp.async.cg.shared.global [%0], [%1], 16;" :: "r"(da), "l"(ga));
                    asm volatile("cp.async.cg.shared.global [%0], [%1], 16;" :: "r"(db), "l"(gb));
                }
                if (tid < 32) {
                    uint32_t ds = sSq + (uint32_t)(buf ^ 1) * 512 + (uint32_t)tid * 16;
                    const void* gs = g_sq1 + nb + tid * 4;
                    asm volatile("cp.async.ca.shared.global [%0], [%1], 16;" :: "r"(ds), "l"(gs));
                }
                asm volatile("cp.async.commit_group;" ::: "memory");
            }
        }

        // --- screen: push flagged off-diag pairs; diag inline ---
        float sqa0 = g_sq1[arow0 + wy * 32 + (lane >> 2)];
        float sqa1 = g_sq1[arow0 + wy * 32 + (lane >> 2) + 8];
        float sqa2 = g_sq1[arow0 + wy * 32 + 16 + (lane >> 2)];
        float sqa3 = g_sq1[arow0 + wy * 32 + 16 + (lane >> 2) + 8];

        float local = 0.0f;
#pragma unroll
        for (int mt = 0; mt < 2; mt++) {
#pragma unroll
            for (int nt = 0; nt < 4; nt++) {
#pragma unroll
                for (int v = 0; v < 4; v++) {
                    int arow = wy * 32 + mt * 16 + (lane >> 2) + 8 * (v >> 1);
                    int col  = wx * 32 + nt * 8 + (lane & 3) * 2 + (v & 1);
                    float sqa = mt ? ((v >> 1) ? sqa3 : sqa2) : ((v >> 1) ? sqa1 : sqa0);
                    float l2s = sqa + sqb[col] - 2.0f * acc[mt][nt][v];
                    if (l2s < SCREEN_T) {
                        int aa = arow0 + arow;
                        int bb = brow0 + col;
                        if (aa == bb) {
                            local += 5.0f;       // k1=1, k0=5 at l2=0
                        } else {
                            uint32_t pos = atomicAdd(qcount, 1u);
                            if (pos < QCAP)
                                queue[pos] = ((uint32_t)arow << 8) | (uint32_t)col;
                            else
                                local += pair_exact_scalar(aa, bb, src0, tar0, src1, tar1);
                        }
                    }
                }
            }
        }
        __syncthreads();

        // --- queue: warp-cooperative exact recompute ---
        uint32_t cnt = *qcount;
        if (cnt > QCAP) cnt = QCAP;
        float wq = 0.0f;
        for (uint32_t q = (uint32_t)wid; q < cnt; q += 16) {
            uint32_t e = queue[q];
            int aa = arow0 + (int)(e >> 8);
            int bb = brow0 + (int)(e & 255u);
            const float* ra1 = (aa < BSZ) ? (src1 + (size_t)aa * D1)
                                          : (tar1 + (size_t)(aa - BSZ) * D1);
            const float* rb1 = (bb < BSZ) ? (src1 + (size_t)bb * D1)
                                          : (tar1 + (size_t)(bb - BSZ) * D1);
            float4 x = ((const float4*)ra1)[lane];
            float4 y = ((const float4*)rb1)[lane];
            float dp1 = x.x * y.x + x.y * y.y + x.z * y.z + x.w * y.w;
#pragma unroll
            for (int off = 16; off; off >>= 1)
                dp1 += __shfl_xor_sync(0xffffffffu, dp1, off);
            float l21 = g_sq1[aa] + g_sq1[bb] - 2.0f * dp1;
            if (l21 < EXACT_T) {
                const float* ra0 = (aa < BSZ) ? (src0 + (size_t)aa * D0)
                                              : (tar0 + (size_t)(aa - BSZ) * D0);
                const float* rb0 = (bb < BSZ) ? (src0 + (size_t)bb * D0)
                                              : (tar0 + (size_t)(bb - BSZ) * D0);
                float dp0 = 0.0f;
#pragma unroll
                for (int it = 0; it < 16; it++) {
                    float4 xx = ((const float4*)ra0)[lane + it * 32];
                    float4 yy = ((const float4*)rb0)[lane + it * 32];
                    dp0 += xx.x * yy.x + xx.y * yy.y + xx.z * yy.z + xx.w * yy.w;
                }
#pragma unroll
                for (int off = 16; off; off >>= 1)
                    dp0 += __shfl_xor_sync(0xffffffffu, dp0, off);
                float l20 = g_sq0[aa] + g_sq0[bb] - 2.0f * dp0;
                float k0v = 0.0f;
#pragma unroll
                for (int qq = 0; qq < 5; qq++)
                    k0v += expf(-l20 * g_inv_bw[qq]);
                if (lane == 0) wq += k0v * expf(-l21 * (1.0f / 1.68f));
            }
        }

        // --- reduce + signed/weighted accumulate ---
#pragma unroll
        for (int off = 16; off; off >>= 1)
            local += __shfl_xor_sync(0xffffffffu, local, off);
        if (lane == 0) wred[wid] = local + wq;
        __syncthreads();
        if (tid == 0) {
            float rsum = 0.0f;
#pragma unroll
            for (int i = 0; i < 16; i++) rsum += wred[i];
            if (rsum != 0.0f) {
                float w   = (bx == by) ? 1.0f : 2.0f;
                float sgn = ((by < NT / 2) == (bx < NT / 2)) ? 1.0f : -1.0f;
                atomicAdd(&g_acc, (double)(rsum * w * sgn));
            }
            *qcount = 0;      // ordered before next screen by the syncs above it
        }
        by = nby; bx = nbx;
    }
}

// ---------------------------------------------------------------------------
// K5: write scalar output
// ---------------------------------------------------------------------------
__global__ void k_out(float* __restrict__ out) {
    out[0] = (float)(g_acc / ((double)BSZ * (double)BSZ));
}

extern "C" void kernel_launch(void* const* d_in, const int* in_sizes, int n_in,
                              void* d_out, int out_size)
{
    const float* src0 = (const float*)d_in[0];
    const float* src1 = (const float*)d_in[1];
    const float* tar0 = (const float*)d_in[2];
    const float* tar1 = (const float*)d_in[3];
    float* out = (float*)d_out;

    cudaFuncSetAttribute(k_tile, cudaFuncAttributeMaxDynamicSharedMemorySize, SM_TOTAL);

    k_pre<<<256, 256>>>(src1, tar1);
    k_f0<<<dim3(8, 64), 256>>>(src0, tar0);
    k_bw<<<1, 1024>>>();
    k_tile<<<PERSIST_GRID, 512, SM_TOTAL>>>(src0, tar0, src1, tar1);
    k_out<<<1, 1>>>(out);
}

// round 10
// speedup vs baseline: 1.1386x; 1.1386x over previous
#include <cuda_runtime.h>
#include <cuda_bf16.h>
#include <math.h>
#include <cstdint>

// Problem constants (fixed by reference setup_inputs)
#define BSZ   4096
#define D0    2048
#define D1    128
#define NTOT  8192
#define TM    128
#define NT    (NTOT / TM)            // 64
#define NTILES_TRI (NT * (NT + 1) / 2)  // 2080
#define PERSIST_GRID 296             // 2 CTAs/SM x 148 SMs
// bf16 screen threshold vs exact threshold (margin covers bf16 dot error ~ +-6).
#define SCREEN_T 145.0f
#define EXACT_T  130.0f

#define SPAD1 136                     // smem row stride (bf16 elems): 272B, 16B-aligned
#define QCAP  1024

// dynamic smem layout (bytes)
#define SM_A     0
#define SM_B     (128 * SPAD1 * 2)                  // 34816
#define SM_SQB   (SM_B + 128 * SPAD1 * 2)           // 69632  (2 buffers x 512B)
#define SM_WRED  (SM_SQB + 1024)                    // 70656  (8 floats)
#define SM_MINB  (SM_WRED + 8 * 4)                  // 70688  (2 floats)
#define SM_QUEUE (SM_MINB + 2 * 4)                  // 70696
#define SM_QCNT  (SM_QUEUE + QCAP * 4)              // 74792
#define SM_TOTAL (SM_QCNT + 32)                     // 74824

// ---- scratch (allocation-free rule: __device__ globals) ----
__device__ float  g_sq0[NTOT];
__device__ float  g_sq1[NTOT];
__device__ float  g_colsum[D0];
__device__ double g_sum_sq0;
__device__ double g_acc;
__device__ float  g_inv_bw[5];
__device__ unsigned g_done_f0;
__device__ unsigned g_done_tile;
__device__ __nv_bfloat16 g_x1[(size_t)NTOT * D1];   // bf16 copy of feature1 (2 MB)

__device__ __forceinline__ uint32_t smem_u32(const void* p) {
    uint32_t a;
    asm("{ .reg .u64 t; cvta.to.shared.u64 t, %1; cvt.u32.u64 %0, t; }"
        : "=r"(a) : "l"(p));
    return a;
}

// Cold path: exact scalar recompute (queue overflow only; keeps hot regs lean)
__device__ __noinline__ float pair_exact_scalar(
    int aa, int bb,
    const float* __restrict__ src0, const float* __restrict__ tar0,
    const float* __restrict__ src1, const float* __restrict__ tar1)
{
    const float* ra1 = (aa < BSZ) ? (src1 + (size_t)aa * D1)
                                  : (tar1 + (size_t)(aa - BSZ) * D1);
    const float* rb1 = (bb < BSZ) ? (src1 + (size_t)bb * D1)
                                  : (tar1 + (size_t)(bb - BSZ) * D1);
    float dp1 = 0.0f;
    for (int dd = 0; dd < D1; dd += 4) {
        float4 x = *(const float4*)(ra1 + dd);
        float4 y = *(const float4*)(rb1 + dd);
        dp1 += x.x * y.x + x.y * y.y + x.z * y.z + x.w * y.w;
    }
    float l21 = g_sq1[aa] + g_sq1[bb] - 2.0f * dp1;
    if (l21 >= EXACT_T) return 0.0f;
    const float* ra0 = (aa < BSZ) ? (src0 + (size_t)aa * D0)
                                  : (tar0 + (size_t)(aa - BSZ) * D0);
    const float* rb0 = (bb < BSZ) ? (src0 + (size_t)bb * D0)
                                  : (tar0 + (size_t)(bb - BSZ) * D0);
    float dp0 = 0.0f;
    for (int dd = 0; dd < D0; dd += 4) {
        float4 x = *(const float4*)(ra0 + dd);
        float4 y = *(const float4*)(rb0 + dd);
        dp0 += x.x * y.x + x.y * y.y + x.z * y.z + x.w * y.w;
    }
    float l20 = g_sq0[aa] + g_sq0[bb] - 2.0f * dp0;
    float k0v = 0.0f;
#pragma unroll
    for (int q = 0; q < 5; q++) k0v += expf(-l20 * g_inv_bw[q]);
    return k0v * expf(-l21 * (1.0f / 1.68f));
}

// ---------------------------------------------------------------------------
// K1: zero accumulators + convert feature1 to bf16 + per-row sq1
// ---------------------------------------------------------------------------
__global__ __launch_bounds__(256) void k_pre(
    const float* __restrict__ src1, const float* __restrict__ tar1)
{
    int bid = blockIdx.x;
    int t = threadIdx.x;
    int w = t >> 5, l = t & 31;

    if (bid < 8)  g_colsum[bid * 256 + t] = 0.0f;
    else if (bid < 40) g_sq0[(bid - 8) * 256 + t] = 0.0f;
    if (bid == 0 && t == 0) {
        g_sum_sq0 = 0.0; g_acc = 0.0;
        g_done_f0 = 0u; g_done_tile = 0u;
    }

    int base = bid * 32 + w * 4;
#pragma unroll
    for (int rr = 0; rr < 4; rr++) {
        int n = base + rr;
        const float* r1 = (n < BSZ) ? (src1 + (size_t)n * D1)
                                    : (tar1 + (size_t)(n - BSZ) * D1);
        float4 v = ((const float4*)r1)[l];
        __nv_bfloat162 lo = __floats2bfloat162_rn(v.x, v.y);
        __nv_bfloat162 hi = __floats2bfloat162_rn(v.z, v.w);
        uint2 pk;
        pk.x = *(uint32_t*)&lo;
        pk.y = *(uint32_t*)&hi;
        *(uint2*)(g_x1 + (size_t)n * D1 + l * 4) = pk;
        float s = v.x * v.x + v.y * v.y + v.z * v.z + v.w * v.w;
#pragma unroll
        for (int off = 16; off; off >>= 1)
            s += __shfl_xor_sync(0xffffffffu, s, off);
        if (l == 0) g_sq1[n] = s;
    }
}

// ---------------------------------------------------------------------------
// K2: fused pass over feature0: row sq0 + col sums + total sq; the LAST CTA
// to finish also computes the bandwidth constants (fused k_bw).
// grid (8, 64): x = 256-col block, y = 128-row chunk.
// ---------------------------------------------------------------------------
__global__ __launch_bounds__(256) void k_f0(
    const float* __restrict__ src0, const float* __restrict__ tar0)
{
    int w = threadIdx.x >> 5, l = threadIdx.x & 31;
    int t = threadIdx.x;
    int d0 = blockIdx.x * 256;
    int nbase = blockIdx.y * 128 + w * 16;
    float colacc[8] = {};
    double wsum = 0.0;
#pragma unroll 2
    for (int rr = 0; rr < 16; rr++) {
        int n = nbase + rr;
        const float* p = (n < BSZ) ? (src0 + (size_t)n * D0)
                                   : (tar0 + (size_t)(n - BSZ) * D0);
        float sq = 0.0f;
#pragma unroll
        for (int j = 0; j < 8; j++) {
            float v = p[d0 + l + j * 32];
            sq += v * v;
            colacc[j] += v;
        }
#pragma unroll
        for (int off = 16; off; off >>= 1)
            sq += __shfl_xor_sync(0xffffffffu, sq, off);
        if (l == 0) { atomicAdd(&g_sq0[n], sq); wsum += (double)sq; }
    }
    if (l == 0) atomicAdd(&g_sum_sq0, wsum);
#pragma unroll
    for (int j = 0; j < 8; j++)
        atomicAdd(&g_colsum[d0 + l + j * 32], colacc[j]);

    // --- last-CTA bandwidth finalize ---
    __shared__ bool isLast;
    __syncthreads();
    if (t == 0) {
        __threadfence();
        unsigned o = atomicAdd(&g_done_f0, 1u);
        isLast = (o == 8u * 64u - 1u);
    }
    __syncthreads();
    if (isLast) {
        double s = 0.0;
#pragma unroll
        for (int j = 0; j < 8; j++) {
            double c = (double)g_colsum[t + j * 256];
            s += c * c;
        }
#pragma unroll
        for (int off = 16; off; off >>= 1)
            s += __shfl_xor_sync(0xffffffffu, s, off);
        __shared__ double red[8];
        if ((t & 31) == 0) red[t >> 5] = s;
        __syncthreads();
        if (t == 0) {
            double tot = 0.0;
#pragma unroll
            for (int i = 0; i < 8; i++) tot += red[i];
            double sum_l2 = 2.0 * (double)NTOT * g_sum_sq0 - 2.0 * tot;
            double bw = sum_l2 / ((double)NTOT * (double)NTOT - (double)NTOT) / 4.0;
#pragma unroll
            for (int i = 0; i < 5; i++)
                g_inv_bw[i] = (float)(1.0 / (bw * (double)(1 << i)));
        }
    }
}

__device__ __forceinline__ void unrank_tri(int idx, int& by, int& bx) {
    int r = (int)((2.0 * NT + 1.0
                   - sqrt((2.0 * NT + 1.0) * (2.0 * NT + 1.0) - 8.0 * idx)) * 0.5);
    if (r < 0) r = 0;
    while (r * NT - r * (r - 1) / 2 > idx) r--;
    while ((r + 1) * NT - (r + 1) * r / 2 <= idx) r++;
    by = r;
    bx = r + (idx - (r * NT - r * (r - 1) / 2));
}

// ---------------------------------------------------------------------------
// K4: persistent bf16 HMMA screening GEMM (256 thr, 8 warps 4x2, warp tile
// 32x64, 2 CTAs/SM) with cross-tile cp.async prefetch, FAST-PATH screen
// (per-thread max-acc bound skips the per-element loop), queue-based
// warp-cooperative exact epilogue. Last CTA writes the final scalar.
// ---------------------------------------------------------------------------
__global__ __launch_bounds__(256, 2) void k_tile(
    const float* __restrict__ src0, const float* __restrict__ tar0,
    const float* __restrict__ src1, const float* __restrict__ tar1,
    float* __restrict__ out)
{
    extern __shared__ char dsm[];
    float*    sqbuf  = (float*)(dsm + SM_SQB);      // [2][128]
    float*    wred   = (float*)(dsm + SM_WRED);
    float*    minb   = (float*)(dsm + SM_MINB);     // [2]
    uint32_t* queue  = (uint32_t*)(dsm + SM_QUEUE);
    uint32_t* qcount = (uint32_t*)(dsm + SM_QCNT);

    int tid = threadIdx.x;
    int wid = tid >> 5, lane = tid & 31;
    int wy = wid >> 1, wx = wid & 1;    // 4x2 warp grid, warp tile 32x64

    uint32_t sAb = smem_u32(dsm + SM_A);
    uint32_t sBb = smem_u32(dsm + SM_B);
    uint32_t sSq = smem_u32(sqbuf);

    uint32_t aRow = (uint32_t)(wy * 32 + (lane & 15));
    uint32_t aKof = (uint32_t)((lane >> 4) * 8);
    uint32_t bRowBase = (uint32_t)(wx * 64 + ((lane >> 3) & 1) * 8 + (lane & 7));
    uint32_t bKof = (uint32_t)((lane >> 4) * 8);

    if (tid == 0) *qcount = 0;

    int idx = blockIdx.x;
    int by, bx;
    unrank_tri(idx, by, bx);

    // initial fill (sq buffer 0)
    {
        int arow0 = by * TM, brow0 = bx * TM;
        for (int c = tid; c < 2048; c += 256) {
            int row = c >> 4, cc = c & 15;
            uint32_t da = sAb + (uint32_t)(row * SPAD1 + cc * 8) * 2;
            uint32_t db = sBb + (uint32_t)(row * SPAD1 + cc * 8) * 2;
            const void* ga = g_x1 + (size_t)(arow0 + row) * D1 + cc * 8;
            const void* gb = g_x1 + (size_t)(brow0 + row) * D1 + cc * 8;
            asm volatile("cp.async.cg.shared.global [%0], [%1], 16;" :: "r"(da), "l"(ga));
            asm volatile("cp.async.cg.shared.global [%0], [%1], 16;" :: "r"(db), "l"(gb));
        }
        if (tid < 32) {
            uint32_t ds = sSq + (uint32_t)tid * 16;
            const void* gs = g_sq1 + brow0 + tid * 4;
            asm volatile("cp.async.ca.shared.global [%0], [%1], 16;" :: "r"(ds), "l"(gs));
        }
        asm volatile("cp.async.commit_group;" ::: "memory");
    }

    int iter = 0;
    for (; idx < NTILES_TRI; idx += PERSIST_GRID, iter++) {
        int buf = iter & 1;
        int arow0 = by * TM, brow0 = bx * TM;
        float* sqb = sqbuf + buf * 128;

        asm volatile("cp.async.wait_group 0;" ::: "memory");
        __syncthreads();

        // per-tile min of sqb (warp 0) -- published by the post-MMA sync
        if (wid == 0) {
            float m = fminf(fminf(sqb[lane], sqb[lane + 32]),
                            fminf(sqb[lane + 64], sqb[lane + 96]));
#pragma unroll
            for (int off = 16; off; off >>= 1)
                m = fminf(m, __shfl_xor_sync(0xffffffffu, m, off));
            if (lane == 0) minb[buf] = m;
        }

        // --- MMA mainloop: 8 K16 steps ---
        float acc[2][8][4];
#pragma unroll
        for (int mt = 0; mt < 2; mt++)
#pragma unroll
            for (int nt = 0; nt < 8; nt++)
#pragma unroll
                for (int v = 0; v < 4; v++) acc[mt][nt][v] = 0.0f;

#pragma unroll
        for (int ks = 0; ks < 8; ks++) {
            uint32_t a[2][4];
#pragma unroll
            for (int mt = 0; mt < 2; mt++) {
                uint32_t addr = sAb + ((aRow + mt * 16) * SPAD1 + ks * 16 + aKof) * 2;
                asm volatile(
                    "ldmatrix.sync.aligned.m8n8.x4.shared.b16 {%0,%1,%2,%3}, [%4];"
                    : "=r"(a[mt][0]), "=r"(a[mt][1]), "=r"(a[mt][2]), "=r"(a[mt][3])
                    : "r"(addr));
            }
            uint32_t b[4][4];
#pragma unroll
            for (int np = 0; np < 4; np++) {
                uint32_t addr = sBb + ((bRowBase + np * 16) * SPAD1 + ks * 16 + bKof) * 2;
                asm volatile(
                    "ldmatrix.sync.aligned.m8n8.x4.shared.b16 {%0,%1,%2,%3}, [%4];"
                    : "=r"(b[np][0]), "=r"(b[np][1]), "=r"(b[np][2]), "=r"(b[np][3])
                    : "r"(addr));
            }
#pragma unroll
            for (int mt = 0; mt < 2; mt++)
#pragma unroll
                for (int nt = 0; nt < 8; nt++) {
                    uint32_t b0 = b[nt >> 1][(nt & 1)];
                    uint32_t b1 = b[nt >> 1][(nt & 1) + 2];
                    float* c = acc[mt][nt];
                    asm volatile(
                        "mma.sync.aligned.m16n8k16.row.col.f32.bf16.bf16.f32 "
                        "{%0,%1,%2,%3}, {%4,%5,%6,%7}, {%8,%9}, {%0,%1,%2,%3};"
                        : "+f"(c[0]), "+f"(c[1]), "+f"(c[2]), "+f"(c[3])
                        : "r"(a[mt][0]), "r"(a[mt][1]), "r"(a[mt][2]), "r"(a[mt][3]),
                          "r"(b0), "r"(b1));
                }
        }
        __syncthreads();   // A/B consumed; minb[buf] visible

        // --- prefetch next tile (overlaps epilogue) ---
        int nby = 0, nbx = 0;
        {
            int nidx = idx + PERSIST_GRID;
            if (nidx < NTILES_TRI) {
                unrank_tri(nidx, nby, nbx);
                int na = nby * TM, nb = nbx * TM;
                for (int c = tid; c < 2048; c += 256) {
                    int row = c >> 4, cc = c & 15;
                    uint32_t da = sAb + (uint32_t)(row * SPAD1 + cc * 8) * 2;
                    uint32_t db = sBb + (uint32_t)(row * SPAD1 + cc * 8) * 2;
                    const void* ga = g_x1 + (size_t)(na + row) * D1 + cc * 8;
                    const void* gb = g_x1 + (size_t)(nb + row) * D1 + cc * 8;
                    asm volatile("cp.async.cg.shared.global [%0], [%1], 16;" :: "r"(da), "l"(ga));
                    asm volatile("cp.async.cg.shared.global [%0], [%1], 16;" :: "r"(db), "l"(gb));
                }
                if (tid < 32) {
                    uint32_t ds = sSq + (uint32_t)(buf ^ 1) * 512 + (uint32_t)tid * 16;
                    const void* gs = g_sq1 + nb + tid * 4;
                    asm volatile("cp.async.ca.shared.global [%0], [%1], 16;" :: "r"(ds), "l"(gs));
                }
                asm volatile("cp.async.commit_group;" ::: "memory");
            }
        }

        // --- screen with fast-path skip ---
        float sqa0 = g_sq1[arow0 + wy * 32 + (lane >> 2)];
        float sqa1 = g_sq1[arow0 + wy * 32 + (lane >> 2) + 8];
        float sqa2 = g_sq1[arow0 + wy * 32 + 16 + (lane >> 2)];
        float sqa3 = g_sq1[arow0 + wy * 32 + 16 + (lane >> 2) + 8];

        float local = 0.0f;
        {
            float maxacc = acc[0][0][0];
#pragma unroll
            for (int mt = 0; mt < 2; mt++)
#pragma unroll
                for (int nt = 0; nt < 8; nt++)
#pragma unroll
                    for (int v = 0; v < 4; v++)
                        maxacc = fmaxf(maxacc, acc[mt][nt][v]);
            float minsqa = fminf(fminf(sqa0, sqa1), fminf(sqa2, sqa3));
            // no element can satisfy l2s < SCREEN_T if this bound holds:
            bool skip = (minsqa + minb[buf] - 2.0f * maxacc) >= SCREEN_T;
            if (!skip) {
#pragma unroll
                for (int mt = 0; mt < 2; mt++) {
#pragma unroll
                    for (int nt = 0; nt < 8; nt++) {
#pragma unroll
                        for (int v = 0; v < 4; v++) {
                            int arow = wy * 32 + mt * 16 + (lane >> 2) + 8 * (v >> 1);
                            int col  = wx * 64 + nt * 8 + (lane & 3) * 2 + (v & 1);
                            float sqa = mt ? ((v >> 1) ? sqa3 : sqa2)
                                           : ((v >> 1) ? sqa1 : sqa0);
                            float l2s = sqa + sqb[col] - 2.0f * acc[mt][nt][v];
                            if (l2s < SCREEN_T) {
                                int aa = arow0 + arow;
                                int bb = brow0 + col;
                                if (aa == bb) {
                                    local += 5.0f;   // k1=1, k0=5 at l2=0
                                } else {
                                    uint32_t pos = atomicAdd(qcount, 1u);
                                    if (pos < QCAP)
                                        queue[pos] = ((uint32_t)arow << 8) | (uint32_t)col;
                                    else
                                        local += pair_exact_scalar(aa, bb, src0, tar0,
                                                                   src1, tar1);
                                }
                            }
                        }
                    }
                }
            }
        }
        __syncthreads();

        // --- queue: warp-cooperative exact recompute ---
        uint32_t cnt = *qcount;
        if (cnt > QCAP) cnt = QCAP;
        float wq = 0.0f;
        for (uint32_t q = (uint32_t)wid; q < cnt; q += 8) {
            uint32_t e = queue[q];
            int aa = arow0 + (int)(e >> 8);
            int bb = brow0 + (int)(e & 255u);
            const float* ra1 = (aa < BSZ) ? (src1 + (size_t)aa * D1)
                                          : (tar1 + (size_t)(aa - BSZ) * D1);
            const float* rb1 = (bb < BSZ) ? (src1 + (size_t)bb * D1)
                                          : (tar1 + (size_t)(bb - BSZ) * D1);
            float4 x = ((const float4*)ra1)[lane];
            float4 y = ((const float4*)rb1)[lane];
            float dp1 = x.x * y.x + x.y * y.y + x.z * y.z + x.w * y.w;
#pragma unroll
            for (int off = 16; off; off >>= 1)
                dp1 += __shfl_xor_sync(0xffffffffu, dp1, off);
            float l21 = g_sq1[aa] + g_sq1[bb] - 2.0f * dp1;
            if (l21 < EXACT_T) {
                const float* ra0 = (aa < BSZ) ? (src0 + (size_t)aa * D0)
                                              : (tar0 + (size_t)(aa - BSZ) * D0);
                const float* rb0 = (bb < BSZ) ? (src0 + (size_t)bb * D0)
                                              : (tar0 + (size_t)(bb - BSZ) * D0);
                float dp0 = 0.0f;
#pragma unroll
                for (int it = 0; it < 16; it++) {
                    float4 xx = ((const float4*)ra0)[lane + it * 32];
                    float4 yy = ((const float4*)rb0)[lane + it * 32];
                    dp0 += xx.x * yy.x + xx.y * yy.y + xx.z * yy.z + xx.w * yy.w;
                }
#pragma unroll
                for (int off = 16; off; off >>= 1)
                    dp0 += __shfl_xor_sync(0xffffffffu, dp0, off);
                float l20 = g_sq0[aa] + g_sq0[bb] - 2.0f * dp0;
                float k0v = 0.0f;
#pragma unroll
                for (int qq = 0; qq < 5; qq++)
                    k0v += expf(-l20 * g_inv_bw[qq]);
                if (lane == 0) wq += k0v * expf(-l21 * (1.0f / 1.68f));
            }
        }

        // --- reduce + signed/weighted accumulate ---
#pragma unroll
        for (int off = 16; off; off >>= 1)
            local += __shfl_xor_sync(0xffffffffu, local, off);
        if (lane == 0) wred[wid] = local + wq;
        __syncthreads();
        if (tid == 0) {
            float rsum = 0.0f;
#pragma unroll
            for (int i = 0; i < 8; i++) rsum += wred[i];
            if (rsum != 0.0f) {
                float w   = (bx == by) ? 1.0f : 2.0f;
                float sgn = ((by < NT / 2) == (bx < NT / 2)) ? 1.0f : -1.0f;
                atomicAdd(&g_acc, (double)(rsum * w * sgn));
            }
            *qcount = 0;      // ordered before next screen by the syncs above it
        }
        by = nby; bx = nbx;
    }

    // --- last persistent CTA writes the final scalar (fused k_out) ---
    __syncthreads();
    if (tid == 0) {
        __threadfence();
        unsigned o = atomicAdd(&g_done_tile, 1u);
        if (o == PERSIST_GRID - 1)
            out[0] = (float)(g_acc / ((double)BSZ * (double)BSZ));
    }
}

extern "C" void kernel_launch(void* const* d_in, const int* in_sizes, int n_in,
                              void* d_out, int out_size)
{
    const float* src0 = (const float*)d_in[0];
    const float* src1 = (const float*)d_in[1];
    const float* tar0 = (const float*)d_in[2];
    const float* tar1 = (const float*)d_in[3];
    float* out = (float*)d_out;

    cudaFuncSetAttribute(k_tile, cudaFuncAttributeMaxDynamicSharedMemorySize, SM_TOTAL);

    k_pre<<<256, 256>>>(src1, tar1);
    k_f0<<<dim3(8, 64), 256>>>(src0, tar0);
    k_tile<<<PERSIST_GRID, 256, SM_TOTAL>>>(src0, tar0, src1, tar1, out);
}